// round 12
// baseline (speedup 1.0000x reference)
#include <cuda_runtime.h>

#define INV_SQRT_2PI 0.3989422804014327f

// A/B isolation: identical shape to the 305.6us best (256t, VPT=4, exact grid),
// but default cache policy (no .cs evict-first hints) — plain LDG.128/STG.128.
// n = 2^28 floats = 2^26 float4 = 65536 blocks * 256 threads * 4 float4/thread.
#define THREADS 256
#define VPT 4  // float4 per thread

__device__ __forceinline__ float hess(float x) {
    float t = x * x;
    return (2.0f - 2.0f * t) * (INV_SQRT_2PI * __expf(-0.5f * t));
}

__global__ void __launch_bounds__(THREADS) hess_gelu_kernel(
    const float4* __restrict__ x, float4* __restrict__ out)
{
    size_t base = (size_t)blockIdx.x * (THREADS * VPT) + threadIdx.x;

    float4 v[VPT];
#pragma unroll
    for (int j = 0; j < VPT; j++) {
        v[j] = x[base + j * THREADS];   // default-policy LDG.E.128
    }

#pragma unroll
    for (int j = 0; j < VPT; j++) {
        v[j].x = hess(v[j].x);
        v[j].y = hess(v[j].y);
        v[j].z = hess(v[j].z);
        v[j].w = hess(v[j].w);
    }

#pragma unroll
    for (int j = 0; j < VPT; j++) {
        out[base + j * THREADS] = v[j]; // default-policy STG.E.128
    }
}

extern "C" void kernel_launch(void* const* d_in, const int* in_sizes, int n_in,
                              void* d_out, int out_size)
{
    const float* x = (const float*)d_in[0];
    float* out = (float*)d_out;
    int n = in_sizes[0];                 // 268435456
    int n4 = n >> 2;                     // 2^26 float4
    int blocks = n4 / (THREADS * VPT);   // 65536, exact
    hess_gelu_kernel<<<blocks, THREADS>>>((const float4*)x, (float4*)out);
}